// round 10
// baseline (speedup 1.0000x reference)
#include <cuda_runtime.h>
#include <cuda_bf16.h>
#include <cstdint>

#define N_NODES 100000
#define N_EDGES 1600000
#define F 128
#define SCAN_B 196      // ceil(100001 / 512)
#define TM 64
#define GEMM_BLOCKS ((N_NODES + TM - 1) / TM)   // 1563
#define N_PAD (GEMM_BLOCKS * TM)                // 100032 (tail rows stay zero)

// ---------------- scratch (static device globals; no cudaMalloc) ------------
__device__ __align__(16) int g_cnt[N_NODES + 1];   // zero-init; scan re-zeroes
__device__ __align__(16) int g_off[N_NODES + 1];
__device__ __align__(16) int g_cur[N_NODES];
__device__ __align__(16) int g_csr[N_EDGES];
__device__ __align__(16) unsigned long long g_desc[SCAN_B];  // lookback state
// agg output, pre-split bf16 hi/lo, pre-swizzled in GEMM smem layout
__device__ __align__(16) unsigned g_thi[(size_t)N_PAD * 64];
__device__ __align__(16) unsigned g_tlo[(size_t)N_PAD * 64];
__device__ __align__(16) float g_m[(size_t)N_NODES * F]; // relu(H) out (fp32)
__device__ __align__(16) float g_bc[2][F];               // b12@W21, b22@W31
// pre-split, transposed (Wt[n][k]), XOR-swizzled weights: [slot][hi/lo][128*128]
__device__ __align__(16) __nv_bfloat16 g_wp[3][2][F * F];

// ---------------- helpers -------------------------------------------------------
__device__ __forceinline__ unsigned pkbf2(float lo, float hi) {
    unsigned r;
    asm("cvt.rn.bf16x2.f32 %0, %1, %2;" : "=r"(r) : "f"(hi), "f"(lo));
    return r;
}
__device__ __forceinline__ unsigned s2u(const void* p) {
    unsigned a;
    asm("{ .reg .u64 t; cvta.to.shared.u64 t, %1; cvt.u32.u64 %0, t; }"
        : "=r"(a) : "l"(p));
    return a;
}
__device__ __forceinline__ void cp16(unsigned smem_addr, const void* gptr) {
    asm volatile("cp.async.cg.shared.global [%0], [%1], 16;" ::
                 "r"(smem_addr), "l"(gptr));
}
__device__ __forceinline__ void cp_commit() { asm volatile("cp.async.commit_group;"); }
__device__ __forceinline__ void cp_wait0()  { asm volatile("cp.async.wait_group 0;"); }

__device__ __forceinline__ void mma16816(float* d, const unsigned* a,
                                         const unsigned* b) {
    asm("mma.sync.aligned.m16n8k16.row.col.f32.bf16.bf16.f32 "
        "{%0,%1,%2,%3}, {%4,%5,%6,%7}, {%8,%9}, {%0,%1,%2,%3};"
        : "+f"(d[0]), "+f"(d[1]), "+f"(d[2]), "+f"(d[3])
        : "r"(a[0]), "r"(a[1]), "r"(a[2]), "r"(a[3]), "r"(b[0]), "r"(b[1]));
}

// swizzled 32-bit word index within a 128-col bf16 row (64 words/row)
__device__ __forceinline__ int swz(int row, int w) {
    return row * 64 + (w ^ ((row & 7) << 2));
}

// ---------------- edge dtype: block-local detection ---------------------------
__device__ __forceinline__ int block_is64(const void* ei, int e) {
    unsigned hw = ((const unsigned*)ei)[2 * e + 1];
    int any = __syncthreads_or(hw != 0u);
    return any ? 0 : 1;
}

// ---------------- CSR build ----------------------------------------------------
__global__ void k_count(const void* __restrict__ ei) {
    if (blockIdx.x == 0 && threadIdx.x < SCAN_B) g_desc[threadIdx.x] = 0ULL;
    int e = blockIdx.x * 256 + threadIdx.x;
    int is64 = block_is64(ei, e);
    int d = is64 ? (int)(((const long long*)ei)[N_EDGES + e])
                 : ((const int*)ei)[N_EDGES + e];
    atomicAdd(&g_cnt[d + 1], 1);
}

// single-kernel decoupled-lookback scan over g_cnt[0..N_NODES] -> g_off, g_cur
__global__ void k_scan_lb() {
    __shared__ int wsum[16];
    __shared__ int s_exc;
    int tid = threadIdx.x, b = blockIdx.x;
    int i = b * 512 + tid;
    int lane = tid & 31, w = tid >> 5;
    int v = (i <= N_NODES) ? g_cnt[i] : 0;
    if (i <= N_NODES) g_cnt[i] = 0;                   // restore invariant
    int s = v;
    #pragma unroll
    for (int o = 1; o < 32; o <<= 1) {
        int t = __shfl_up_sync(0xffffffffu, s, o);
        if (lane >= o) s += t;
    }
    if (lane == 31) wsum[w] = s;
    __syncthreads();
    if (w == 0) {
        int ws = (lane < 16) ? wsum[lane] : 0;
        #pragma unroll
        for (int o = 1; o < 16; o <<= 1) {
            int t = __shfl_up_sync(0xffffffffu, ws, o);
            if (lane >= o) ws += t;
        }
        if (lane < 16) wsum[lane] = ws;
    }
    __syncthreads();
    int incl = s + (w > 0 ? wsum[w - 1] : 0);
    int total = wsum[15];
    if (tid == 0) {
        unsigned long long pub =
            ((unsigned long long)(b == 0 ? 2u : 1u) << 32) | (unsigned)total;
        atomicExch(&g_desc[b], pub);
    }
    int exc = 0;
    if (b > 0) {
        if (tid == 0) {
            int p = b - 1, run = 0;
            while (true) {
                unsigned long long d = atomicAdd(&g_desc[p], 0ULL);
                unsigned f = (unsigned)(d >> 32);
                if (f == 0u) continue;
                run += (int)(d & 0xffffffffu);
                if (f == 2u) break;
                p--;
            }
            s_exc = run;
            atomicExch(&g_desc[b], (2ULL << 32) | (unsigned)(run + total));
        }
        __syncthreads();
        exc = s_exc;
    }
    if (i <= N_NODES) {
        int val = exc + incl;
        g_off[i] = val;
        if (i < N_NODES) g_cur[i] = val;
    }
}

__global__ void k_fill(const void* __restrict__ ei) {
    int e = blockIdx.x * 256 + threadIdx.x;
    int is64 = block_is64(ei, e);
    int s, d;
    if (is64) {
        s = (int)(((const long long*)ei)[e]);
        d = (int)(((const long long*)ei)[N_EDGES + e]);
    } else {
        s = ((const int*)ei)[e];
        d = ((const int*)ei)[N_EDGES + e];
    }
    int p = atomicAdd(&g_cur[d], 1);
    g_csr[p] = s;
}

// ---------------- weight prep: combine + split + swizzle (one kernel) -----------
// slot 0: W = w11 ; slot 1: W = w12@w21, bc0 = b12@w21 ; slot 2: W = w22@w31,
// bc1 = b22@w31. Output g_wp[slot] (transposed Wt[n][k], hi/lo, swizzled).
__global__ void __launch_bounds__(512, 1)
k_wprep(const float* __restrict__ w11,
        const float* __restrict__ w12, const float* __restrict__ b12,
        const float* __restrict__ w21,
        const float* __restrict__ w22, const float* __restrict__ b22,
        const float* __restrict__ w31) {
    extern __shared__ float sW[];   // F*F fp32, layout [k][j]
    int slot = blockIdx.x;
    int tid = threadIdx.x;
    if (slot == 0) {
        for (int i = tid; i < F * F; i += 512) sW[i] = w11[i];
    } else {
        const float* A  = (slot == 1) ? w12 : w22;
        const float* bA = (slot == 1) ? b12 : b22;
        const float* B  = (slot == 1) ? w21 : w31;
        for (int o = tid; o < F * F; o += 512) {
            int k = o >> 7, j = o & 127;
            float s = 0.f;
            #pragma unroll 4
            for (int m = 0; m < F; m++) s += A[k * F + m] * B[m * F + j];
            sW[o] = s;
        }
        if (tid < F) {
            float s = 0.f;
            #pragma unroll 4
            for (int m = 0; m < F; m++) s += bA[m] * B[m * F + tid];
            g_bc[slot - 1][tid] = s;
        }
    }
    __syncthreads();
    __nv_bfloat16* dhi = &g_wp[slot][0][0];
    __nv_bfloat16* dlo = &g_wp[slot][1][0];
    for (int idx = tid; idx < F * F; idx += 512) {
        int n = idx >> 7, k = idx & 127;
        float v = sW[k * F + n];
        __nv_bfloat16 h = __float2bfloat16(v);
        float l = v - __bfloat162float(h);
        int e = swz(n, k >> 1) * 2 + (k & 1);
        dhi[e] = h;
        dlo[e] = __float2bfloat16(l);
    }
}

// ---------------- aggregation + split: g_thi/g_tlo[i] = split(in[i]+sum nbrs) ---
// Output layout matches GEMM smem exactly: row node, word (2l)^((node&7)<<2).
__global__ void k_agg(const float* __restrict__ x, int layer) {
    const float* in = (layer == 0) ? x : (const float*)g_m;
    int w = (blockIdx.x * blockDim.x + threadIdx.x) >> 5;
    if (w >= N_NODES) return;
    int lane = threadIdx.x & 31;
    const float4* xin = (const float4*)in;
    float4 acc = xin[(size_t)w * 32 + lane];
    int e = g_off[w];
    int end = g_off[w + 1];
    for (; e + 4 <= end; e += 4) {
        int s0 = g_csr[e], s1 = g_csr[e + 1], s2 = g_csr[e + 2], s3 = g_csr[e + 3];
        float4 v0 = xin[(size_t)s0 * 32 + lane];
        float4 v1 = xin[(size_t)s1 * 32 + lane];
        float4 v2 = xin[(size_t)s2 * 32 + lane];
        float4 v3 = xin[(size_t)s3 * 32 + lane];
        acc.x += (v0.x + v1.x) + (v2.x + v3.x);
        acc.y += (v0.y + v1.y) + (v2.y + v3.y);
        acc.z += (v0.z + v1.z) + (v2.z + v3.z);
        acc.w += (v0.w + v1.w) + (v2.w + v3.w);
    }
    for (; e < end; e++) {
        int s0 = g_csr[e];
        float4 v0 = xin[(size_t)s0 * 32 + lane];
        acc.x += v0.x; acc.y += v0.y; acc.z += v0.z; acc.w += v0.w;
    }
    // split to bf16 hi/lo and store pre-swizzled
    __nv_bfloat16 bx = __float2bfloat16(acc.x);
    __nv_bfloat16 by = __float2bfloat16(acc.y);
    __nv_bfloat16 bz = __float2bfloat16(acc.z);
    __nv_bfloat16 bw = __float2bfloat16(acc.w);
    uint2 HI, LO;
    HI.x = ((unsigned)__bfloat16_as_ushort(by) << 16) | __bfloat16_as_ushort(bx);
    HI.y = ((unsigned)__bfloat16_as_ushort(bw) << 16) | __bfloat16_as_ushort(bz);
    LO.x = pkbf2(acc.x - __bfloat162float(bx), acc.y - __bfloat162float(by));
    LO.y = pkbf2(acc.z - __bfloat162float(bz), acc.w - __bfloat162float(bw));
    int wordp = (2 * lane) ^ ((w & 7) << 2);
    *(uint2*)(g_thi + (size_t)w * 64 + wordp) = HI;
    *(uint2*)(g_tlo + (size_t)w * 64 + wordp) = LO;
}

// ---------------- tensor-core GEMM: H = relu(t @ W + bias), tile 64x128 ---------
// A arrives pre-split/pre-swizzled in g_thi/g_tlo -> pure cp.async prologue.
// bias[col] = bias1[col] + (1+deg_row)*g_bc[bc_sel-1][col]  (bc_sel=0: none)
// dot_mode: outS[n] = H[n,:].w32 + b32 ; else g_m[n,:] = H[n,:]
#define SM_TOT (2 * TM * F * 2 + 2 * F * F * 2 + 3 * F * 4)
__global__ void __launch_bounds__(128, 2)
k_gemm_mma(int slot, const float* __restrict__ bias1, int bc_sel, int dot_mode,
           const float* __restrict__ w32, const float* __restrict__ b32,
           float* __restrict__ outS) {
    extern __shared__ __align__(16) char smem[];
    __nv_bfloat16* sAhi = (__nv_bfloat16*)smem;            // 16 KB
    __nv_bfloat16* sAlo = sAhi + TM * F;                   // 16 KB
    __nv_bfloat16* sBhi = sAlo + TM * F;                   // 64 KB (hi then lo)
    float* sBias1 = (float*)(sBhi + 2 * F * F);
    float* sBiasC = sBias1 + F;
    float* sW32   = sBiasC + F;

    float* out = (float*)g_m;

    int tid = threadIdx.x;
    int lane = tid & 31, wid = tid >> 5;
    int nbase = blockIdx.x * TM;

    // ---- B (Wt hi+lo, pre-swizzled): linear 64 KB cp.async ----
    unsigned sB = s2u(sBhi);
    const char* gb = (const char*)&g_wp[slot][0][0];
    #pragma unroll
    for (int i = 0; i < 32; i++)
        cp16(sB + (tid + i * 128) * 16, gb + (size_t)(tid + i * 128) * 16);
    // ---- A (pre-split, pre-swizzled): linear 2 x 16 KB cp.async ----
    unsigned sAh = s2u(sAhi);
    unsigned sAl = s2u(sAlo);
    const char* gah = (const char*)(g_thi + (size_t)nbase * 64);
    const char* gal = (const char*)(g_tlo + (size_t)nbase * 64);
    #pragma unroll
    for (int i = 0; i < 8; i++) {
        cp16(sAh + (tid + i * 128) * 16, gah + (size_t)(tid + i * 128) * 16);
        cp16(sAl + (tid + i * 128) * 16, gal + (size_t)(tid + i * 128) * 16);
    }
    cp_commit();
    if (tid < F) {
        sBias1[tid] = bias1[tid];
        sBiasC[tid] = bc_sel ? g_bc[bc_sel - 1][tid] : 0.f;
        sW32[tid]   = dot_mode ? w32[tid] : 0.f;
    }
    cp_wait0();
    __syncthreads();

    const unsigned* uAhi = (const unsigned*)sAhi;
    const unsigned* uAlo = (const unsigned*)sAlo;
    const unsigned* uBhi = (const unsigned*)sBhi;
    const unsigned* uBlo = uBhi + F * F / 2;

    float acc[16][4];
    #pragma unroll
    for (int i = 0; i < 16; i++)
        #pragma unroll
        for (int j = 0; j < 4; j++) acc[i][j] = 0.f;

    int g = lane >> 2;        // group id 0..7
    int t = lane & 3;         // thread in group
    int m0 = wid * 16 + g;    // fragment row (lower 8), 0..63

    #pragma unroll
    for (int s = 0; s < 8; s++) {
        int w0 = 8 * s + t, w1 = w0 + 4;
        unsigned ahi[4], alo[4];
        ahi[0] = uAhi[swz(m0, w0)];     ahi[1] = uAhi[swz(m0 + 8, w0)];
        ahi[2] = uAhi[swz(m0, w1)];     ahi[3] = uAhi[swz(m0 + 8, w1)];
        alo[0] = uAlo[swz(m0, w0)];     alo[1] = uAlo[swz(m0 + 8, w0)];
        alo[2] = uAlo[swz(m0, w1)];     alo[3] = uAlo[swz(m0 + 8, w1)];
        #pragma unroll
        for (int nt = 0; nt < 16; nt++) {
            int n0 = nt * 8 + g;
            unsigned bh[2], bl[2];
            bh[0] = uBhi[swz(n0, w0)];  bh[1] = uBhi[swz(n0, w1)];
            bl[0] = uBlo[swz(n0, w0)];  bl[1] = uBlo[swz(n0, w1)];
            mma16816(acc[nt], ahi, bh);
            mma16816(acc[nt], ahi, bl);
            mma16816(acc[nt], alo, bh);
        }
    }

    // ---- epilogue ----
    int node0 = nbase + m0;
    int node1 = node0 + 8;
    float sc0 = 0.f, sc1 = 0.f;
    if (bc_sel) {
        if (node0 < N_NODES) sc0 = 1.f + (float)(g_off[node0 + 1] - g_off[node0]);
        if (node1 < N_NODES) sc1 = 1.f + (float)(g_off[node1 + 1] - g_off[node1]);
    }
    if (!dot_mode) {
        #pragma unroll
        for (int nt = 0; nt < 16; nt++) {
            int col = nt * 8 + 2 * t;
            float bx = sBias1[col], by = sBias1[col + 1];
            float cx = sBiasC[col], cy = sBiasC[col + 1];
            float2 o0, o1;
            o0.x = fmaxf(acc[nt][0] + bx + sc0 * cx, 0.f);
            o0.y = fmaxf(acc[nt][1] + by + sc0 * cy, 0.f);
            o1.x = fmaxf(acc[nt][2] + bx + sc1 * cx, 0.f);
            o1.y = fmaxf(acc[nt][3] + by + sc1 * cy, 0.f);
            if (node0 < N_NODES) *(float2*)(out + (size_t)node0 * F + col) = o0;
            if (node1 < N_NODES) *(float2*)(out + (size_t)node1 * F + col) = o1;
        }
    } else {
        float p0 = 0.f, p1 = 0.f;
        #pragma unroll
        for (int nt = 0; nt < 16; nt++) {
            int col = nt * 8 + 2 * t;
            float bx = sBias1[col], by = sBias1[col + 1];
            float cx = sBiasC[col], cy = sBiasC[col + 1];
            p0 += fmaxf(acc[nt][0] + bx + sc0 * cx, 0.f) * sW32[col]
                + fmaxf(acc[nt][1] + by + sc0 * cy, 0.f) * sW32[col + 1];
            p1 += fmaxf(acc[nt][2] + bx + sc1 * cx, 0.f) * sW32[col]
                + fmaxf(acc[nt][3] + by + sc1 * cy, 0.f) * sW32[col + 1];
        }
        p0 += __shfl_xor_sync(0xffffffffu, p0, 1);
        p0 += __shfl_xor_sync(0xffffffffu, p0, 2);
        p1 += __shfl_xor_sync(0xffffffffu, p1, 1);
        p1 += __shfl_xor_sync(0xffffffffu, p1, 2);
        if (t == 0) {
            float bb = b32[0];
            if (node0 < N_NODES) outS[node0] = p0 + bb;
            if (node1 < N_NODES) outS[node1] = p1 + bb;
        }
    }
}

// ---------------- launch ---------------------------------------------------------
extern "C" void kernel_launch(void* const* d_in, const int* in_sizes, int n_in,
                              void* d_out, int out_size) {
    const float* x = (const float*)d_in[0];
    const void* ei = d_in[1];
    const float* w11 = (const float*)d_in[2];
    const float* b11 = (const float*)d_in[3];
    const float* w12 = (const float*)d_in[4];
    const float* b12 = (const float*)d_in[5];
    const float* w21 = (const float*)d_in[6];
    const float* b21 = (const float*)d_in[7];
    const float* w22 = (const float*)d_in[8];
    const float* b22 = (const float*)d_in[9];
    const float* w31 = (const float*)d_in[10];
    const float* b31 = (const float*)d_in[11];
    const float* w32 = (const float*)d_in[12];
    const float* b32 = (const float*)d_in[13];
    float* out = (float*)d_out;

    static int smem_set = 0;
    if (!smem_set) {
        cudaFuncSetAttribute(k_gemm_mma, cudaFuncAttributeMaxDynamicSharedMemorySize,
                             SM_TOT);
        cudaFuncSetAttribute(k_wprep, cudaFuncAttributeMaxDynamicSharedMemorySize,
                             F * F * 4);
        smem_set = 1;
    }

    const int AGG_BLOCKS = (N_NODES * 32 + 255) / 256;   // warp per node

    k_count<<<N_EDGES / 256, 256>>>(ei);                              // 1
    k_scan_lb<<<SCAN_B, 512>>>();                                     // 2
    k_fill<<<N_EDGES / 256, 256>>>(ei);                               // 3
    k_wprep<<<3, 512, F * F * 4>>>(w11, w12, b12, w21, w22, b22, w31);// 4
    k_agg<<<AGG_BLOCKS, 256>>>(x, 0);                                 // 5
    // H1 = relu(agg(x)@W11 + b11)                                    // 6 <- ncu
    k_gemm_mma<<<GEMM_BLOCKS, 128, SM_TOT>>>(0, b11, 0, 0, w32, b32, out);
    // H2 = relu(agg(H1)@Wc2 + (1+deg)bc2 + b21)
    k_agg<<<AGG_BLOCKS, 256>>>(x, 1);
    k_gemm_mma<<<GEMM_BLOCKS, 128, SM_TOT>>>(1, b21, 1, 0, w32, b32, out);
    // out = relu(agg(H2)@Wc3 + (1+deg)bc3 + b31) . w32 + b32
    k_agg<<<AGG_BLOCKS, 256>>>(x, 2);
    k_gemm_mma<<<GEMM_BLOCKS, 128, SM_TOT>>>(2, b31, 2, 1, w32, b32, out);
}

// round 11
// speedup vs baseline: 1.2526x; 1.2526x over previous
#include <cuda_runtime.h>
#include <cuda_bf16.h>
#include <cstdint>

#define N_NODES 100000
#define N_EDGES 1600000
#define F 128
#define SCAN_B 196      // ceil(100001 / 512)
#define TM 64
#define GEMM_BLOCKS ((N_NODES + TM - 1) / TM)   // 1563
#define N_PAD (GEMM_BLOCKS * TM)                // 100032 (tail rows stay zero)

// ---------------- scratch (static device globals; no cudaMalloc) ------------
__device__ __align__(16) int g_cnt[N_NODES + 1];   // zero-init; scan re-zeroes
__device__ __align__(16) int g_off[N_NODES + 1];
__device__ __align__(16) int g_cur[N_NODES];
__device__ __align__(16) int g_csr[N_EDGES];
__device__ __align__(16) unsigned long long g_desc[SCAN_B];  // lookback state
// agg output, pre-split bf16 hi/lo, pre-swizzled in GEMM smem layout
__device__ __align__(16) unsigned g_thi[(size_t)N_PAD * 64];
__device__ __align__(16) unsigned g_tlo[(size_t)N_PAD * 64];
__device__ __align__(16) float g_m[(size_t)N_NODES * F]; // relu(H) out (fp32)
__device__ __align__(16) float g_wc[2][F * F];           // W12@W21, W22@W31 (fp32)
__device__ __align__(16) float g_bc[2][F];               // b12@W21, b22@W31
// pre-split, transposed (Wt[n][k]), XOR-swizzled weights: [slot][hi/lo][128*128]
__device__ __align__(16) __nv_bfloat16 g_wp[3][2][F * F];

// ---------------- helpers -------------------------------------------------------
__device__ __forceinline__ unsigned pkbf2(float lo, float hi) {
    unsigned r;
    asm("cvt.rn.bf16x2.f32 %0, %1, %2;" : "=r"(r) : "f"(hi), "f"(lo));
    return r;
}
__device__ __forceinline__ unsigned s2u(const void* p) {
    unsigned a;
    asm("{ .reg .u64 t; cvta.to.shared.u64 t, %1; cvt.u32.u64 %0, t; }"
        : "=r"(a) : "l"(p));
    return a;
}
__device__ __forceinline__ void cp16(unsigned smem_addr, const void* gptr) {
    asm volatile("cp.async.cg.shared.global [%0], [%1], 16;" ::
                 "r"(smem_addr), "l"(gptr));
}
__device__ __forceinline__ void cp_commit() { asm volatile("cp.async.commit_group;"); }
__device__ __forceinline__ void cp_wait0()  { asm volatile("cp.async.wait_group 0;"); }

__device__ __forceinline__ void mma16816(float* d, const unsigned* a,
                                         const unsigned* b) {
    asm("mma.sync.aligned.m16n8k16.row.col.f32.bf16.bf16.f32 "
        "{%0,%1,%2,%3}, {%4,%5,%6,%7}, {%8,%9}, {%0,%1,%2,%3};"
        : "+f"(d[0]), "+f"(d[1]), "+f"(d[2]), "+f"(d[3])
        : "r"(a[0]), "r"(a[1]), "r"(a[2]), "r"(a[3]), "r"(b[0]), "r"(b[1]));
}

// swizzled 32-bit word index within a 128-col bf16 row (64 words/row)
__device__ __forceinline__ int swz(int row, int w) {
    return row * 64 + (w ^ ((row & 7) << 2));
}

// ---------------- edge dtype: block-local detection ---------------------------
__device__ __forceinline__ int block_is64(const void* ei, int e) {
    unsigned hw = ((const unsigned*)ei)[2 * e + 1];
    int any = __syncthreads_or(hw != 0u);
    return any ? 0 : 1;
}

// ---------------- CSR build ----------------------------------------------------
__global__ void k_count(const void* __restrict__ ei) {
    if (blockIdx.x == 0 && threadIdx.x < SCAN_B) g_desc[threadIdx.x] = 0ULL;
    int e = blockIdx.x * 256 + threadIdx.x;
    int is64 = block_is64(ei, e);
    int d = is64 ? (int)(((const long long*)ei)[N_EDGES + e])
                 : ((const int*)ei)[N_EDGES + e];
    atomicAdd(&g_cnt[d + 1], 1);
}

// single-kernel decoupled-lookback scan over g_cnt[0..N_NODES] -> g_off, g_cur
__global__ void k_scan_lb() {
    __shared__ int wsum[16];
    __shared__ int s_exc;
    int tid = threadIdx.x, b = blockIdx.x;
    int i = b * 512 + tid;
    int lane = tid & 31, w = tid >> 5;
    int v = (i <= N_NODES) ? g_cnt[i] : 0;
    if (i <= N_NODES) g_cnt[i] = 0;                   // restore invariant
    int s = v;
    #pragma unroll
    for (int o = 1; o < 32; o <<= 1) {
        int t = __shfl_up_sync(0xffffffffu, s, o);
        if (lane >= o) s += t;
    }
    if (lane == 31) wsum[w] = s;
    __syncthreads();
    if (w == 0) {
        int ws = (lane < 16) ? wsum[lane] : 0;
        #pragma unroll
        for (int o = 1; o < 16; o <<= 1) {
            int t = __shfl_up_sync(0xffffffffu, ws, o);
            if (lane >= o) ws += t;
        }
        if (lane < 16) wsum[lane] = ws;
    }
    __syncthreads();
    int incl = s + (w > 0 ? wsum[w - 1] : 0);
    int total = wsum[15];
    if (tid == 0) {
        unsigned long long pub =
            ((unsigned long long)(b == 0 ? 2u : 1u) << 32) | (unsigned)total;
        atomicExch(&g_desc[b], pub);
    }
    int exc = 0;
    if (b > 0) {
        if (tid == 0) {
            int p = b - 1, run = 0;
            while (true) {
                unsigned long long d = atomicAdd(&g_desc[p], 0ULL);
                unsigned f = (unsigned)(d >> 32);
                if (f == 0u) continue;
                run += (int)(d & 0xffffffffu);
                if (f == 2u) break;
                p--;
            }
            s_exc = run;
            atomicExch(&g_desc[b], (2ULL << 32) | (unsigned)(run + total));
        }
        __syncthreads();
        exc = s_exc;
    }
    if (i <= N_NODES) {
        int val = exc + incl;
        g_off[i] = val;
        if (i < N_NODES) g_cur[i] = val;
    }
}

__global__ void k_fill(const void* __restrict__ ei) {
    int e = blockIdx.x * 256 + threadIdx.x;
    int is64 = block_is64(ei, e);
    int s, d;
    if (is64) {
        s = (int)(((const long long*)ei)[e]);
        d = (int)(((const long long*)ei)[N_EDGES + e]);
    } else {
        s = ((const int*)ei)[e];
        d = ((const int*)ei)[N_EDGES + e];
    }
    int p = atomicAdd(&g_cur[d], 1);
    g_csr[p] = s;
}

// ---------------- aggregation + split: g_thi/g_tlo[i] = split(in[i]+sum nbrs) ---
// Output layout matches GEMM smem exactly: row node, word (2l)^((node&7)<<2).
__global__ void k_agg(const float* __restrict__ x, int layer) {
    const float* in = (layer == 0) ? x : (const float*)g_m;
    int w = (blockIdx.x * blockDim.x + threadIdx.x) >> 5;
    if (w >= N_NODES) return;
    int lane = threadIdx.x & 31;
    const float4* xin = (const float4*)in;
    float4 acc = xin[(size_t)w * 32 + lane];
    int e = g_off[w];
    int end = g_off[w + 1];
    for (; e + 4 <= end; e += 4) {
        int s0 = g_csr[e], s1 = g_csr[e + 1], s2 = g_csr[e + 2], s3 = g_csr[e + 3];
        float4 v0 = xin[(size_t)s0 * 32 + lane];
        float4 v1 = xin[(size_t)s1 * 32 + lane];
        float4 v2 = xin[(size_t)s2 * 32 + lane];
        float4 v3 = xin[(size_t)s3 * 32 + lane];
        acc.x += (v0.x + v1.x) + (v2.x + v3.x);
        acc.y += (v0.y + v1.y) + (v2.y + v3.y);
        acc.z += (v0.z + v1.z) + (v2.z + v3.z);
        acc.w += (v0.w + v1.w) + (v2.w + v3.w);
    }
    for (; e < end; e++) {
        int s0 = g_csr[e];
        float4 v0 = xin[(size_t)s0 * 32 + lane];
        acc.x += v0.x; acc.y += v0.y; acc.z += v0.z; acc.w += v0.w;
    }
    // split to bf16 hi/lo and store pre-swizzled
    __nv_bfloat16 bx = __float2bfloat16(acc.x);
    __nv_bfloat16 by = __float2bfloat16(acc.y);
    __nv_bfloat16 bz = __float2bfloat16(acc.z);
    __nv_bfloat16 bw = __float2bfloat16(acc.w);
    uint2 HI, LO;
    HI.x = ((unsigned)__bfloat16_as_ushort(by) << 16) | __bfloat16_as_ushort(bx);
    HI.y = ((unsigned)__bfloat16_as_ushort(bw) << 16) | __bfloat16_as_ushort(bz);
    LO.x = pkbf2(acc.x - __bfloat162float(bx), acc.y - __bfloat162float(by));
    LO.y = pkbf2(acc.z - __bfloat162float(bz), acc.w - __bfloat162float(bw));
    int wordp = (2 * lane) ^ ((w & 7) << 2);
    *(uint2*)(g_thi + (size_t)w * 64 + wordp) = HI;
    *(uint2*)(g_tlo + (size_t)w * 64 + wordp) = LO;
}

// ---------------- combined weights: Wc = A@B (fp32), bc = bA@B ------------------
// 16 blocks: prod = b>>3, row group = b&7 (16 rows each). ~10 us.
__global__ void k_wcombine(const float* __restrict__ w12, const float* __restrict__ b12,
                           const float* __restrict__ w21, const float* __restrict__ w22,
                           const float* __restrict__ b22, const float* __restrict__ w31) {
    int prod = blockIdx.x >> 3, rowg = blockIdx.x & 7;
    const float* A  = prod ? w22 : w12;
    const float* bA = prod ? b22 : b12;
    const float* B  = prod ? w31 : w21;
    float* C  = g_wc[prod];
    float* bc = g_bc[prod];
    for (int idx = threadIdx.x; idx < 16 * F; idx += blockDim.x) {
        int k = rowg * 16 + (idx >> 7);
        int j = idx & 127;
        float s = 0.f;
        #pragma unroll 4
        for (int m = 0; m < F; m++) s += A[k * F + m] * B[m * F + j];
        C[k * F + j] = s;
    }
    if (rowg == 0 && threadIdx.x < F) {
        int j = threadIdx.x;
        float s = 0.f;
        #pragma unroll 4
        for (int m = 0; m < F; m++) s += bA[m] * B[m * F + j];
        bc[j] = s;
    }
}

// ---------------- weight prep: W[k][j] -> Wt_hi/lo[n=j][k], swizzled (split only)
__global__ void k_wprep(const float* __restrict__ w11) {
    const float* W = (blockIdx.x == 0) ? w11 : g_wc[blockIdx.x - 1];
    __nv_bfloat16* dhi = &g_wp[blockIdx.x][0][0];
    __nv_bfloat16* dlo = &g_wp[blockIdx.x][1][0];
    for (int idx = threadIdx.x; idx < F * F; idx += blockDim.x) {
        int n = idx >> 7, k = idx & 127;
        float v = W[k * F + n];
        __nv_bfloat16 h = __float2bfloat16(v);
        float l = v - __bfloat162float(h);
        int e = swz(n, k >> 1) * 2 + (k & 1);
        dhi[e] = h;
        dlo[e] = __float2bfloat16(l);
    }
}

// ---------------- tensor-core GEMM: H = relu(t @ W + bias), tile 64x128 ---------
// A arrives pre-split/pre-swizzled in g_thi/g_tlo -> pure cp.async prologue.
// bias[col] = bias1[col] + (1+deg_row)*g_bc[bc_sel-1][col]  (bc_sel=0: none)
// dot_mode: outS[n] = H[n,:].w32 + b32 ; else g_m[n,:] = H[n,:]
#define SM_TOT (2 * TM * F * 2 + 2 * F * F * 2 + 3 * F * 4)
__global__ void __launch_bounds__(128, 2)
k_gemm_mma(int slot, const float* __restrict__ bias1, int bc_sel, int dot_mode,
           const float* __restrict__ w32, const float* __restrict__ b32,
           float* __restrict__ outS) {
    extern __shared__ __align__(16) char smem[];
    __nv_bfloat16* sAhi = (__nv_bfloat16*)smem;            // 16 KB
    __nv_bfloat16* sAlo = sAhi + TM * F;                   // 16 KB
    __nv_bfloat16* sBhi = sAlo + TM * F;                   // 64 KB (hi then lo)
    float* sBias1 = (float*)(sBhi + 2 * F * F);
    float* sBiasC = sBias1 + F;
    float* sW32   = sBiasC + F;

    float* out = (float*)g_m;

    int tid = threadIdx.x;
    int lane = tid & 31, wid = tid >> 5;
    int nbase = blockIdx.x * TM;

    // ---- B (Wt hi+lo, pre-swizzled): linear 64 KB cp.async ----
    unsigned sB = s2u(sBhi);
    const char* gb = (const char*)&g_wp[slot][0][0];
    #pragma unroll
    for (int i = 0; i < 32; i++)
        cp16(sB + (tid + i * 128) * 16, gb + (size_t)(tid + i * 128) * 16);
    // ---- A (pre-split, pre-swizzled): linear 2 x 16 KB cp.async ----
    unsigned sAh = s2u(sAhi);
    unsigned sAl = s2u(sAlo);
    const char* gah = (const char*)(g_thi + (size_t)nbase * 64);
    const char* gal = (const char*)(g_tlo + (size_t)nbase * 64);
    #pragma unroll
    for (int i = 0; i < 8; i++) {
        cp16(sAh + (tid + i * 128) * 16, gah + (size_t)(tid + i * 128) * 16);
        cp16(sAl + (tid + i * 128) * 16, gal + (size_t)(tid + i * 128) * 16);
    }
    cp_commit();
    if (tid < F) {
        sBias1[tid] = bias1[tid];
        sBiasC[tid] = bc_sel ? g_bc[bc_sel - 1][tid] : 0.f;
        sW32[tid]   = dot_mode ? w32[tid] : 0.f;
    }
    cp_wait0();
    __syncthreads();

    const unsigned* uAhi = (const unsigned*)sAhi;
    const unsigned* uAlo = (const unsigned*)sAlo;
    const unsigned* uBhi = (const unsigned*)sBhi;
    const unsigned* uBlo = uBhi + F * F / 2;

    float acc[16][4];
    #pragma unroll
    for (int i = 0; i < 16; i++)
        #pragma unroll
        for (int j = 0; j < 4; j++) acc[i][j] = 0.f;

    int g = lane >> 2;        // group id 0..7
    int t = lane & 3;         // thread in group
    int m0 = wid * 16 + g;    // fragment row (lower 8), 0..63

    #pragma unroll
    for (int s = 0; s < 8; s++) {
        int w0 = 8 * s + t, w1 = w0 + 4;
        unsigned ahi[4], alo[4];
        ahi[0] = uAhi[swz(m0, w0)];     ahi[1] = uAhi[swz(m0 + 8, w0)];
        ahi[2] = uAhi[swz(m0, w1)];     ahi[3] = uAhi[swz(m0 + 8, w1)];
        alo[0] = uAlo[swz(m0, w0)];     alo[1] = uAlo[swz(m0 + 8, w0)];
        alo[2] = uAlo[swz(m0, w1)];     alo[3] = uAlo[swz(m0 + 8, w1)];
        #pragma unroll
        for (int nt = 0; nt < 16; nt++) {
            int n0 = nt * 8 + g;
            unsigned bh[2], bl[2];
            bh[0] = uBhi[swz(n0, w0)];  bh[1] = uBhi[swz(n0, w1)];
            bl[0] = uBlo[swz(n0, w0)];  bl[1] = uBlo[swz(n0, w1)];
            mma16816(acc[nt], ahi, bh);
            mma16816(acc[nt], ahi, bl);
            mma16816(acc[nt], alo, bh);
        }
    }

    // ---- epilogue ----
    int node0 = nbase + m0;
    int node1 = node0 + 8;
    float sc0 = 0.f, sc1 = 0.f;
    if (bc_sel) {
        if (node0 < N_NODES) sc0 = 1.f + (float)(g_off[node0 + 1] - g_off[node0]);
        if (node1 < N_NODES) sc1 = 1.f + (float)(g_off[node1 + 1] - g_off[node1]);
    }
    if (!dot_mode) {
        #pragma unroll
        for (int nt = 0; nt < 16; nt++) {
            int col = nt * 8 + 2 * t;
            float bx = sBias1[col], by = sBias1[col + 1];
            float cx = sBiasC[col], cy = sBiasC[col + 1];
            float2 o0, o1;
            o0.x = fmaxf(acc[nt][0] + bx + sc0 * cx, 0.f);
            o0.y = fmaxf(acc[nt][1] + by + sc0 * cy, 0.f);
            o1.x = fmaxf(acc[nt][2] + bx + sc1 * cx, 0.f);
            o1.y = fmaxf(acc[nt][3] + by + sc1 * cy, 0.f);
            if (node0 < N_NODES) *(float2*)(out + (size_t)node0 * F + col) = o0;
            if (node1 < N_NODES) *(float2*)(out + (size_t)node1 * F + col) = o1;
        }
    } else {
        float p0 = 0.f, p1 = 0.f;
        #pragma unroll
        for (int nt = 0; nt < 16; nt++) {
            int col = nt * 8 + 2 * t;
            float bx = sBias1[col], by = sBias1[col + 1];
            float cx = sBiasC[col], cy = sBiasC[col + 1];
            p0 += fmaxf(acc[nt][0] + bx + sc0 * cx, 0.f) * sW32[col]
                + fmaxf(acc[nt][1] + by + sc0 * cy, 0.f) * sW32[col + 1];
            p1 += fmaxf(acc[nt][2] + bx + sc1 * cx, 0.f) * sW32[col]
                + fmaxf(acc[nt][3] + by + sc1 * cy, 0.f) * sW32[col + 1];
        }
        p0 += __shfl_xor_sync(0xffffffffu, p0, 1);
        p0 += __shfl_xor_sync(0xffffffffu, p0, 2);
        p1 += __shfl_xor_sync(0xffffffffu, p1, 1);
        p1 += __shfl_xor_sync(0xffffffffu, p1, 2);
        if (t == 0) {
            float bb = b32[0];
            if (node0 < N_NODES) outS[node0] = p0 + bb;
            if (node1 < N_NODES) outS[node1] = p1 + bb;
        }
    }
}

// ---------------- launch ---------------------------------------------------------
extern "C" void kernel_launch(void* const* d_in, const int* in_sizes, int n_in,
                              void* d_out, int out_size) {
    const float* x = (const float*)d_in[0];
    const void* ei = d_in[1];
    const float* w11 = (const float*)d_in[2];
    const float* b11 = (const float*)d_in[3];
    const float* w12 = (const float*)d_in[4];
    const float* b12 = (const float*)d_in[5];
    const float* w21 = (const float*)d_in[6];
    const float* b21 = (const float*)d_in[7];
    const float* w22 = (const float*)d_in[8];
    const float* b22 = (const float*)d_in[9];
    const float* w31 = (const float*)d_in[10];
    const float* b31 = (const float*)d_in[11];
    const float* w32 = (const float*)d_in[12];
    const float* b32 = (const float*)d_in[13];
    float* out = (float*)d_out;

    static int smem_set = 0;
    if (!smem_set) {
        cudaFuncSetAttribute(k_gemm_mma, cudaFuncAttributeMaxDynamicSharedMemorySize,
                             SM_TOT);
        smem_set = 1;
    }

    const int AGG_BLOCKS = (N_NODES * 32 + 255) / 256;   // warp per node

    k_count<<<N_EDGES / 256, 256>>>(ei);      // 1 (also zeroes lookback state)
    k_scan_lb<<<SCAN_B, 512>>>();             // 2
    k_fill<<<N_EDGES / 256, 256>>>(ei);       // 3
    k_agg<<<AGG_BLOCKS, 256>>>(x, 0);         // 4  <- ncu capture slot
    k_wcombine<<<16, 256>>>(w12, b12, w21, w22, b22, w31);  // 5 (~10 us, parallel)
    k_wprep<<<3, 256>>>(w11);                 // 6 (split/swizzle only, ~4 us)

    // H1 = relu(agg(x)@W11 + b11)
    k_gemm_mma<<<GEMM_BLOCKS, 128, SM_TOT>>>(0, b11, 0, 0, w32, b32, out);
    // H2 = relu(agg(H1)@Wc2 + (1+deg)bc2 + b21)
    k_agg<<<AGG_BLOCKS, 256>>>(x, 1);
    k_gemm_mma<<<GEMM_BLOCKS, 128, SM_TOT>>>(1, b21, 1, 0, w32, b32, out);
    // out = relu(agg(H2)@Wc3 + (1+deg)bc3 + b31) . w32 + b32
    k_agg<<<AGG_BLOCKS, 256>>>(x, 2);
    k_gemm_mma<<<GEMM_BLOCKS, 128, SM_TOT>>>(2, b31, 2, 1, w32, b32, out);
}